// round 2
// baseline (speedup 1.0000x reference)
#include <cuda_runtime.h>
#include <math.h>

// ---------------- problem constants (fixed by dataset) ----------------
#define N_NODES 50000
#define N_REL   50
#define N_BASES 30
#define F_DIN   64            // din is 64 for all three layers
#define NSEG    (N_NODES * N_REL)          // 2,500,000
#define MAXE    1100000
#define SCAN_CHUNK 2048
#define NB_SCAN ((NSEG + SCAN_CHUNK - 1) / SCAN_CHUNK)   // 1221

// ---------------- static device scratch (no allocations) ----------------
__device__ int   d_cnt[NSEG];
__device__ int   d_off[NSEG + 1];
__device__ int   d_cpt[NSEG + 1];
__device__ int   d_cur[NSEG];
__device__ int   d_seglist[MAXE];
__device__ int   d_perm[MAXE];
__device__ int   d_part1[NB_SCAN + 1];
__device__ int   d_part2[NB_SCAN + 1];
__device__ float d_W[N_REL * 64 * 64];     // combined per-relation weights
__device__ float d_msg[N_NODES * 64];
__device__ float d_hA[N_NODES * 64];
__device__ float d_hB[N_NODES * 64];

// ---------------- setup kernels ----------------
__global__ void k_zero_cnt() {
    int i = blockIdx.x * blockDim.x + threadIdx.x;
    if (i < NSEG) d_cnt[i] = 0;
}

__global__ void k_hist(const int* __restrict__ et, const int* __restrict__ dst, int E) {
    int e = blockIdx.x * blockDim.x + threadIdx.x;
    if (e < E) atomicAdd(&d_cnt[et[e] * N_NODES + dst[e]], 1);
}

// block-level exclusive scans of (cnt, cnt>0), 2048 elems per block
__global__ void k_scan1() {
    int t = threadIdx.x;
    int base = blockIdx.x * SCAN_CHUNK + t * 8;
    int v[8], f[8];
    int run1 = 0, run2 = 0;
#pragma unroll
    for (int j = 0; j < 8; j++) {
        int idx = base + j;
        int c = (idx < NSEG) ? d_cnt[idx] : 0;
        v[j] = run1; f[j] = run2;
        run1 += c; run2 += (c > 0);
    }
    __shared__ int sh[256], shc[256];
    sh[t] = run1; shc[t] = run2;
    __syncthreads();
    for (int d = 1; d < 256; d <<= 1) {
        int a = 0, b = 0;
        if (t >= d) { a = sh[t - d]; b = shc[t - d]; }
        __syncthreads();
        if (t >= d) { sh[t] += a; shc[t] += b; }
        __syncthreads();
    }
    int ex1 = sh[t] - run1, ex2 = shc[t] - run2;
#pragma unroll
    for (int j = 0; j < 8; j++) {
        int idx = base + j;
        if (idx < NSEG) { d_off[idx] = ex1 + v[j]; d_cpt[idx] = ex2 + f[j]; }
    }
    if (t == 255) { d_part1[blockIdx.x] = sh[255]; d_part2[blockIdx.x] = shc[255]; }
}

__global__ void k_scan2() {   // single block: exclusive scan of block partials
    __shared__ int sh[256], shc[256];
    __shared__ int carry1, carry2;
    int t = threadIdx.x;
    if (t == 0) { carry1 = 0; carry2 = 0; }
    __syncthreads();
    for (int b = 0; b < NB_SCAN; b += 256) {
        int i = b + t;
        int v1 = (i < NB_SCAN) ? d_part1[i] : 0;
        int v2 = (i < NB_SCAN) ? d_part2[i] : 0;
        sh[t] = v1; shc[t] = v2;
        __syncthreads();
        for (int d = 1; d < 256; d <<= 1) {
            int a = 0, c = 0;
            if (t >= d) { a = sh[t - d]; c = shc[t - d]; }
            __syncthreads();
            if (t >= d) { sh[t] += a; shc[t] += c; }
            __syncthreads();
        }
        if (i < NB_SCAN) {
            d_part1[i] = carry1 + sh[t] - v1;
            d_part2[i] = carry2 + shc[t] - v2;
        }
        __syncthreads();
        if (t == 0) { carry1 += sh[255]; carry2 += shc[255]; }
        __syncthreads();
    }
}

__global__ void k_scan3() {   // add block offsets; also mirror off -> cursor
    int p1 = d_part1[blockIdx.x], p2 = d_part2[blockIdx.x];
    int base = blockIdx.x * SCAN_CHUNK;
    for (int i = threadIdx.x; i < SCAN_CHUNK; i += 256) {
        int idx = base + i;
        if (idx < NSEG) {
            int o = d_off[idx] + p1;
            d_off[idx] = o;
            d_cur[idx] = o;
            d_cpt[idx] += p2;
        }
    }
}

__global__ void k_final(int E) {
    d_off[NSEG] = E;
    d_cpt[NSEG] = d_cpt[NSEG - 1] + (d_cnt[NSEG - 1] > 0 ? 1 : 0);
}

__global__ void k_seglist() {
    int s = blockIdx.x * blockDim.x + threadIdx.x;
    if (s < NSEG && d_cnt[s] > 0) d_seglist[d_cpt[s]] = s;
}

__global__ void k_perm(const int* __restrict__ et, const int* __restrict__ dst, int E) {
    int e = blockIdx.x * blockDim.x + threadIdx.x;
    if (e < E) {
        int key = et[e] * N_NODES + dst[e];
        int p = atomicAdd(&d_cur[key], 1);
        d_perm[p] = e;
    }
}

// ---------------- per-layer kernels ----------------
// W[r,k,o] = sum_b comp[r,b] * bases[b,k,o]
__global__ void k_W(const float* __restrict__ bases, const float* __restrict__ comp, int dout) {
    int idx = blockIdx.x * blockDim.x + threadIdx.x;
    int tot = N_REL * 64 * dout;
    if (idx >= tot) return;
    int r = idx / (64 * dout);
    int ko = idx - r * 64 * dout;
    float acc = 0.f;
#pragma unroll 6
    for (int b = 0; b < N_BASES; b++)
        acc += comp[r * N_BASES + b] * bases[b * 64 * dout + ko];
    d_W[idx] = acc;
}

// msg = x @ root + bias   (initializes the accumulator for the relation GEMMs)
__global__ void k_init(const float* __restrict__ x, const float* __restrict__ root,
                       const float* __restrict__ bias, int dout) {
    int idx = blockIdx.x * blockDim.x + threadIdx.x;
    if (idx >= N_NODES * dout) return;
    int n = idx / dout, o = idx - n * dout;
    float acc = bias[o];
    const float* xr = x + n * 64;
#pragma unroll 16
    for (int i = 0; i < 64; i++) acc += xr[i] * root[i * dout + o];
    d_msg[idx] = acc;
}

// Fused: per-relation mean aggregation (from CSR) + [64 x 64] x [64 x DOUT] transform
// + RED accumulation into msg. One block = 64 nonempty segments of one relation.
template <int DOUT>
__global__ void __launch_bounds__(256) k_agg_gemm(const float* __restrict__ x,
                                                  const int* __restrict__ src) {
    __shared__ float As[64][68];
    __shared__ float Wt[DOUT][68];   // transposed: Wt[o][k]
    __shared__ int   sdst[64];
    int r = blockIdx.y;
    int t = threadIdx.x;
    int baseC = d_cpt[r * N_NODES];
    int m_r = d_cpt[(r + 1) * N_NODES] - baseC;
    int row0 = blockIdx.x * 64;
    if (row0 >= m_r) return;

    const float* Wr = d_W + r * 64 * DOUT;
    for (int i = t; i < 64 * DOUT; i += 256) {
        int k = i / DOUT, o = i - k * DOUT;
        Wt[o][k] = Wr[i];
    }

    int lane = t & 31, w = t >> 5;
    for (int rr = w; rr < 64; rr += 8) {
        int row = row0 + rr;
        float s0 = 0.f, s1 = 0.f;
        int dn = -1;
        if (row < m_r) {
            int seg = d_seglist[baseC + row];
            dn = seg - r * N_NODES;
            int e0 = d_off[seg], e1 = d_off[seg + 1];
            for (int e = e0; e < e1; e++) {
                int sn = src[d_perm[e]];
                s0 += __ldg(&x[sn * 64 + lane]);
                s1 += __ldg(&x[sn * 64 + lane + 32]);
            }
            float inv = 1.0f / (float)(e1 - e0);
            s0 *= inv; s1 *= inv;
        }
        As[rr][lane] = s0;
        As[rr][lane + 32] = s1;
        if (lane == 0) sdst[rr] = dn;
    }
    __syncthreads();

    if (DOUT == 64) {
        int tx = t & 15, ty = t >> 4;
        float acc[4][4];
#pragma unroll
        for (int i = 0; i < 4; i++)
#pragma unroll
            for (int j = 0; j < 4; j++) acc[i][j] = 0.f;
#pragma unroll
        for (int k = 0; k < 64; k += 4) {
            float4 a[4], b[4];
#pragma unroll
            for (int i = 0; i < 4; i++) a[i] = *(const float4*)&As[ty + i * 16][k];
#pragma unroll
            for (int j = 0; j < 4; j++) b[j] = *(const float4*)&Wt[tx + j * 16][k];
#pragma unroll
            for (int i = 0; i < 4; i++)
#pragma unroll
                for (int j = 0; j < 4; j++)
                    acc[i][j] += a[i].x * b[j].x + a[i].y * b[j].y +
                                 a[i].z * b[j].z + a[i].w * b[j].w;
        }
#pragma unroll
        for (int i = 0; i < 4; i++) {
            int rr = ty + i * 16;
            int dn = sdst[rr];
            if (dn >= 0) {
#pragma unroll
                for (int j = 0; j < 4; j++)
                    atomicAdd(&d_msg[dn * 64 + tx + j * 16], acc[i][j]);
            }
        }
    } else {  // DOUT == 8
        int row = t >> 2;
        int c0 = (t & 3) * 2;
        float a0 = 0.f, a1 = 0.f;
#pragma unroll
        for (int k = 0; k < 64; k++) {
            float a = As[row][k];
            a0 += a * Wt[c0][k];
            a1 += a * Wt[c0 + 1][k];
        }
        int dn = sdst[row];
        if (dn >= 0) {
            atomicAdd(&d_msg[dn * 8 + c0], a0);
            atomicAdd(&d_msg[dn * 8 + c0 + 1], a1);
        }
    }
}

__global__ void k_relu(float* __restrict__ h) {
    int i = blockIdx.x * blockDim.x + threadIdx.x;
    if (i < N_NODES * 64) {
        float v = d_msg[i];
        h[i] = v > 0.f ? v : 0.f;
    }
}

__global__ void k_lsm(float* __restrict__ out) {
    int n = blockIdx.x * blockDim.x + threadIdx.x;
    if (n >= N_NODES) return;
    float v[8];
    float m = -1e30f;
#pragma unroll
    for (int c = 0; c < 8; c++) {
        v[c] = d_msg[n * 8 + c];
        m = fmaxf(m, v[c]);
    }
    float s = 0.f;
#pragma unroll
    for (int c = 0; c < 8; c++) s += expf(v[c] - m);
    float ls = logf(s) + m;
#pragma unroll
    for (int c = 0; c < 8; c++) out[n * 8 + c] = v[c] - ls;
}

// ---------------- launch ----------------
extern "C" void kernel_launch(void* const* d_in, const int* in_sizes, int n_in,
                              void* d_out, int out_size) {
    const float* x0 = (const float*)d_in[0];
    const int* ei = (const int*)d_in[1];
    const int* et = (const int*)d_in[2];
    int E = in_sizes[2];
    const int* src = ei;        // edge_index[0]
    const int* dst = ei + E;    // edge_index[1]

    void *pA, *pB;
    cudaGetSymbolAddress(&pA, d_hA);
    cudaGetSymbolAddress(&pB, d_hB);
    float* hA = (float*)pA;
    float* hB = (float*)pB;

    // ---- CSR build over key = rel*N + dst (shared by all 3 layers) ----
    k_zero_cnt<<<(NSEG + 255) / 256, 256>>>();
    k_hist<<<(E + 255) / 256, 256>>>(et, dst, E);
    k_scan1<<<NB_SCAN, 256>>>();
    k_scan2<<<1, 256>>>();
    k_scan3<<<NB_SCAN, 256>>>();
    k_final<<<1, 1>>>(E);
    k_seglist<<<(NSEG + 255) / 256, 256>>>();
    k_perm<<<(E + 255) / 256, 256>>>(et, dst, E);

    const float* xin = x0;
    dim3 grid((N_NODES + 63) / 64, N_REL);

    for (int l = 0; l < 3; l++) {
        const float* bases = (const float*)d_in[3 + 4 * l];
        const float* comp  = (const float*)d_in[4 + 4 * l];
        const float* root  = (const float*)d_in[5 + 4 * l];
        const float* bias  = (const float*)d_in[6 + 4 * l];
        int dout = (l == 2) ? 8 : 64;

        k_W<<<(N_REL * 64 * dout + 255) / 256, 256>>>(bases, comp, dout);
        k_init<<<(N_NODES * dout + 255) / 256, 256>>>(xin, root, bias, dout);
        if (dout == 64) k_agg_gemm<64><<<grid, 256>>>(xin, src);
        else            k_agg_gemm<8><<<grid, 256>>>(xin, src);

        if (l == 0)      { k_relu<<<(N_NODES * 64 + 255) / 256, 256>>>(hA); xin = hA; }
        else if (l == 1) { k_relu<<<(N_NODES * 64 + 255) / 256, 256>>>(hB); xin = hB; }
        else             { k_lsm<<<(N_NODES + 255) / 256, 256>>>((float*)d_out); }
    }
}

// round 3
// speedup vs baseline: 1.4055x; 1.4055x over previous
#include <cuda_runtime.h>
#include <math.h>
#include <stdint.h>

// ---------------- problem constants ----------------
#define N_NODES 50000
#define N_REL   50
#define N_BASES 30
#define NSEG    (N_NODES * N_REL)
#define MAXE    1100000
#define SCAN_CHUNK 2048
#define NB_SCAN ((NSEG + SCAN_CHUNK - 1) / SCAN_CHUNK)

// ---------------- static device scratch ----------------
__device__ int   d_cnt[NSEG];
__device__ int   d_off[NSEG + 1];
__device__ int   d_cpt[NSEG + 1];
__device__ int   d_cur[NSEG];
__device__ int   d_coff[MAXE + 2];   // compact CSR offsets
__device__ int   d_cdst[MAXE];      // compact segment -> dst node
__device__ int   d_srcn[MAXE];      // sorted edge -> src node
__device__ int   d_part1[NB_SCAN + 1];
__device__ int   d_part2[NB_SCAN + 1];
__device__ float d_W[N_REL * 64 * 64];
__device__ float d_msg[N_NODES * 64];
__device__ float d_hA[N_NODES * 64];
__device__ float d_hB[N_NODES * 64];

__device__ __forceinline__ float tf32r(float v) {
    uint32_t u;
    asm("cvt.rna.tf32.f32 %0, %1;" : "=r"(u) : "f"(v));
    return __uint_as_float(u);
}

// ---------------- setup kernels ----------------
__global__ void k_zero_cnt() {
    int i = blockIdx.x * blockDim.x + threadIdx.x;
    if (i < NSEG) d_cnt[i] = 0;
}

__global__ void k_hist(const int* __restrict__ et, const int* __restrict__ dst, int E) {
    int e = blockIdx.x * blockDim.x + threadIdx.x;
    if (e < E) atomicAdd(&d_cnt[et[e] * N_NODES + dst[e]], 1);
}

__global__ void k_scan1() {
    int t = threadIdx.x;
    int base = blockIdx.x * SCAN_CHUNK + t * 8;
    int v[8], f[8];
    int run1 = 0, run2 = 0;
#pragma unroll
    for (int j = 0; j < 8; j++) {
        int idx = base + j;
        int c = (idx < NSEG) ? d_cnt[idx] : 0;
        v[j] = run1; f[j] = run2;
        run1 += c; run2 += (c > 0);
    }
    __shared__ int sh[256], shc[256];
    sh[t] = run1; shc[t] = run2;
    __syncthreads();
    for (int d = 1; d < 256; d <<= 1) {
        int a = 0, b = 0;
        if (t >= d) { a = sh[t - d]; b = shc[t - d]; }
        __syncthreads();
        if (t >= d) { sh[t] += a; shc[t] += b; }
        __syncthreads();
    }
    int ex1 = sh[t] - run1, ex2 = shc[t] - run2;
#pragma unroll
    for (int j = 0; j < 8; j++) {
        int idx = base + j;
        if (idx < NSEG) { d_off[idx] = ex1 + v[j]; d_cpt[idx] = ex2 + f[j]; }
    }
    if (t == 255) { d_part1[blockIdx.x] = sh[255]; d_part2[blockIdx.x] = shc[255]; }
}

__global__ void k_scan2() {
    __shared__ int sh[256], shc[256];
    __shared__ int carry1, carry2;
    int t = threadIdx.x;
    if (t == 0) { carry1 = 0; carry2 = 0; }
    __syncthreads();
    for (int b = 0; b < NB_SCAN; b += 256) {
        int i = b + t;
        int v1 = (i < NB_SCAN) ? d_part1[i] : 0;
        int v2 = (i < NB_SCAN) ? d_part2[i] : 0;
        sh[t] = v1; shc[t] = v2;
        __syncthreads();
        for (int d = 1; d < 256; d <<= 1) {
            int a = 0, c = 0;
            if (t >= d) { a = sh[t - d]; c = shc[t - d]; }
            __syncthreads();
            if (t >= d) { sh[t] += a; shc[t] += c; }
            __syncthreads();
        }
        if (i < NB_SCAN) {
            d_part1[i] = carry1 + sh[t] - v1;
            d_part2[i] = carry2 + shc[t] - v2;
        }
        __syncthreads();
        if (t == 0) { carry1 += sh[255]; carry2 += shc[255]; }
        __syncthreads();
    }
}

__global__ void k_scan3() {
    int p1 = d_part1[blockIdx.x], p2 = d_part2[blockIdx.x];
    int base = blockIdx.x * SCAN_CHUNK;
    for (int i = threadIdx.x; i < SCAN_CHUNK; i += 256) {
        int idx = base + i;
        if (idx < NSEG) {
            int o = d_off[idx] + p1;
            d_off[idx] = o;
            d_cur[idx] = o;
            d_cpt[idx] += p2;
        }
    }
}

__global__ void k_final(int E) {
    d_off[NSEG] = E;
    int ct = d_cpt[NSEG - 1] + (d_cnt[NSEG - 1] > 0 ? 1 : 0);
    d_cpt[NSEG] = ct;
    d_coff[ct] = E;
}

__global__ void k_compact() {
    int s = blockIdx.x * blockDim.x + threadIdx.x;
    if (s < NSEG && d_cnt[s] > 0) {
        int c = d_cpt[s];
        d_coff[c] = d_off[s];
        d_cdst[c] = s % N_NODES;
    }
}

__global__ void k_scatter(const int* __restrict__ et, const int* __restrict__ dst,
                          const int* __restrict__ src, int E) {
    int e = blockIdx.x * blockDim.x + threadIdx.x;
    if (e < E) {
        int key = et[e] * N_NODES + dst[e];
        int p = atomicAdd(&d_cur[key], 1);
        d_srcn[p] = src[e];
    }
}

// ---------------- per-layer kernels ----------------
// W[r,k,o] = sum_b comp[r,b] * bases[b,k,o], pre-rounded to tf32
__global__ void k_W(const float* __restrict__ bases, const float* __restrict__ comp, int dout) {
    int idx = blockIdx.x * blockDim.x + threadIdx.x;
    int tot = N_REL * 64 * dout;
    if (idx >= tot) return;
    int r = idx / (64 * dout);
    int ko = idx - r * 64 * dout;
    float acc = 0.f;
#pragma unroll 6
    for (int b = 0; b < N_BASES; b++)
        acc += comp[r * N_BASES + b] * bases[b * 64 * dout + ko];
    d_W[idx] = tf32r(acc);
}

// msg = x @ root + bias (exact fp32 accumulator base)
__global__ void k_init(const float* __restrict__ x, const float* __restrict__ root,
                       const float* __restrict__ bias, int dout) {
    int idx = blockIdx.x * blockDim.x + threadIdx.x;
    if (idx >= N_NODES * dout) return;
    int n = idx / dout, o = idx - n * dout;
    float acc = bias[o];
    const float* xr = x + n * 64;
#pragma unroll 16
    for (int i = 0; i < 64; i++) acc += xr[i] * root[i * dout + o];
    d_msg[idx] = acc;
}

// Fused per-relation mean aggregation + transform + RED accumulation.
// Block = 128 compact segments of one relation; warp owns 16 rows (one m16 tile).
// Edges of a warp's 16 rows are CONTIGUOUS in d_srcn (counting-sort order),
// so the warp streams one edge range with register accumulation + row flush.
template <int DOUT>
__global__ void __launch_bounds__(256) k_agg(const float* __restrict__ x) {
    constexpr int WS = (DOUT == 64) ? 68 : 8;
    extern __shared__ float smem[];
    float* Ws = smem;                       // [64][WS]
    float* As = smem + 64 * WS;             // [128][68]  tf32-rounded means
    int* sdst = (int*)(As + 128 * 68);      // [128]
    int* soB  = sdst + 128;                 // [8][17]

    int r = blockIdx.y;
    int t = threadIdx.x, lane = t & 31, w = t >> 5;
    int* so = soB + w * 17;

    int baseC = d_cpt[r * N_NODES];
    int Cend  = d_cpt[(r + 1) * N_NODES];
    int row0  = blockIdx.x * 128;
    if (baseC + row0 >= Cend) return;

    // load (pre-rounded) W_r
    const float* Wr = d_W + r * 64 * DOUT;
    if (DOUT == 64) {
        for (int i = t; i < 64 * 64; i += 256)
            Ws[(i >> 6) * 68 + (i & 63)] = Wr[i];
    } else {
        for (int i = t; i < 64 * 8; i += 256) Ws[i] = Wr[i];
    }

    // per-warp row metadata
    int cbase = baseC + row0 + w * 16;
    if (lane <= 16) so[lane] = d_coff[min(cbase + lane, Cend)];
    if (lane < 16) {
        int ci = cbase + lane;
        sdst[w * 16 + lane] = (ci < Cend) ? d_cdst[ci] : -1;
    }
    // zero my 16 rows
    float* myA = As + (w * 16) * 68;
#pragma unroll
    for (int i = 0; i < 16; i++) {
        myA[i * 68 + 2 * lane] = 0.f;
        myA[i * 68 + 2 * lane + 1] = 0.f;
    }
    __syncwarp();

    // streamed edge accumulation (lane owns feature cols 2*lane, 2*lane+1)
    int e0 = so[0], e1 = so[16];
    if (e1 > e0) {
        int ptr = 0;
        int cur = so[0], nxt = so[1];
        float a0 = 0.f, a1 = 0.f;
        for (int e = e0; e < e1; ++e) {
            if (e >= nxt) {
                int c = nxt - cur;
                if (c > 0) {
                    float inv = 1.f / (float)c;
                    myA[ptr * 68 + 2 * lane]     = tf32r(a0 * inv);
                    myA[ptr * 68 + 2 * lane + 1] = tf32r(a1 * inv);
                }
                a0 = 0.f; a1 = 0.f;
                do { ptr++; } while (e >= so[ptr + 1]);
                cur = so[ptr]; nxt = so[ptr + 1];
            }
            int sn = d_srcn[e];
            float2 xv = *(const float2*)(x + sn * 64 + 2 * lane);
            a0 += xv.x; a1 += xv.y;
        }
        float inv = 1.f / (float)(nxt - cur);
        myA[ptr * 68 + 2 * lane]     = tf32r(a0 * inv);
        myA[ptr * 68 + 2 * lane + 1] = tf32r(a1 * inv);
    }
    __syncthreads();   // Ws visible; As is warp-private

    if (DOUT == 64) {
        // tf32 HMMA: m16n8k8, warp tile = 16 rows x 64 cols, K=64
        int g = lane >> 2, q = lane & 3;
        const float* Ar0 = As + (w * 16 + g) * 68;
        const float* Ar8 = Ar0 + 8 * 68;
        float acc[8][4];
#pragma unroll
        for (int j = 0; j < 8; j++)
#pragma unroll
            for (int i = 0; i < 4; i++) acc[j][i] = 0.f;
#pragma unroll
        for (int kk = 0; kk < 8; kk++) {
            int k0 = kk * 8;
            uint32_t A0 = __float_as_uint(Ar0[k0 + q]);
            uint32_t A1 = __float_as_uint(Ar8[k0 + q]);
            uint32_t A2 = __float_as_uint(Ar0[k0 + q + 4]);
            uint32_t A3 = __float_as_uint(Ar8[k0 + q + 4]);
#pragma unroll
            for (int j = 0; j < 8; j++) {
                uint32_t B0 = __float_as_uint(Ws[(k0 + q) * 68 + j * 8 + g]);
                uint32_t B1 = __float_as_uint(Ws[(k0 + q + 4) * 68 + j * 8 + g]);
                asm volatile(
                    "mma.sync.aligned.m16n8k8.row.col.f32.tf32.tf32.f32 "
                    "{%0,%1,%2,%3}, {%4,%5,%6,%7}, {%8,%9}, {%0,%1,%2,%3};"
                    : "+f"(acc[j][0]), "+f"(acc[j][1]), "+f"(acc[j][2]), "+f"(acc[j][3])
                    : "r"(A0), "r"(A1), "r"(A2), "r"(A3), "r"(B0), "r"(B1));
            }
        }
        int dA = sdst[w * 16 + g];
        int dB = sdst[w * 16 + g + 8];
#pragma unroll
        for (int j = 0; j < 8; j++) {
            int col = j * 8 + 2 * q;
            if (dA >= 0) {
                atomicAdd(&d_msg[dA * 64 + col],     acc[j][0]);
                atomicAdd(&d_msg[dA * 64 + col + 1], acc[j][1]);
            }
            if (dB >= 0) {
                atomicAdd(&d_msg[dB * 64 + col],     acc[j][2]);
                atomicAdd(&d_msg[dB * 64 + col + 1], acc[j][3]);
            }
        }
    } else {
        // DOUT == 8 : SIMT, lane pair per row, 4 cols per lane
        int row = lane >> 1;
        int c0 = (lane & 1) * 4;
        const float* Ar = As + (w * 16 + row) * 68;
        float s0 = 0.f, s1 = 0.f, s2 = 0.f, s3 = 0.f;
#pragma unroll
        for (int k = 0; k < 64; k++) {
            float a = Ar[k];
            float4 b = *(const float4*)&Ws[k * 8 + c0];
            s0 += a * b.x; s1 += a * b.y; s2 += a * b.z; s3 += a * b.w;
        }
        int dn = sdst[w * 16 + row];
        if (dn >= 0) {
            atomicAdd(&d_msg[dn * 8 + c0],     s0);
            atomicAdd(&d_msg[dn * 8 + c0 + 1], s1);
            atomicAdd(&d_msg[dn * 8 + c0 + 2], s2);
            atomicAdd(&d_msg[dn * 8 + c0 + 3], s3);
        }
    }
}

__global__ void k_relu(float* __restrict__ h) {
    int i = blockIdx.x * blockDim.x + threadIdx.x;
    if (i < N_NODES * 64) {
        float v = d_msg[i];
        h[i] = v > 0.f ? v : 0.f;
    }
}

__global__ void k_lsm(float* __restrict__ out) {
    int n = blockIdx.x * blockDim.x + threadIdx.x;
    if (n >= N_NODES) return;
    float v[8];
    float m = -1e30f;
#pragma unroll
    for (int c = 0; c < 8; c++) {
        v[c] = d_msg[n * 8 + c];
        m = fmaxf(m, v[c]);
    }
    float s = 0.f;
#pragma unroll
    for (int c = 0; c < 8; c++) s += expf(v[c] - m);
    float ls = logf(s) + m;
#pragma unroll
    for (int c = 0; c < 8; c++) out[n * 8 + c] = v[c] - ls;
}

// ---------------- launch ----------------
extern "C" void kernel_launch(void* const* d_in, const int* in_sizes, int n_in,
                              void* d_out, int out_size) {
    const float* x0 = (const float*)d_in[0];
    const int* ei = (const int*)d_in[1];
    const int* et = (const int*)d_in[2];
    int E = in_sizes[2];
    const int* src = ei;
    const int* dst = ei + E;

    void *pA, *pB;
    cudaGetSymbolAddress(&pA, d_hA);
    cudaGetSymbolAddress(&pB, d_hB);
    float* hA = (float*)pA;
    float* hB = (float*)pB;

    const int SMEM64 = (64 * 68 + 128 * 68) * 4 + 128 * 4 + 8 * 17 * 4;
    const int SMEM8  = (64 * 8  + 128 * 68) * 4 + 128 * 4 + 8 * 17 * 4;
    cudaFuncSetAttribute(k_agg<64>, cudaFuncAttributeMaxDynamicSharedMemorySize, SMEM64);
    cudaFuncSetAttribute(k_agg<8>,  cudaFuncAttributeMaxDynamicSharedMemorySize, SMEM8);

    // ---- CSR build over key = rel*N + dst ----
    k_zero_cnt<<<(NSEG + 255) / 256, 256>>>();
    k_hist<<<(E + 255) / 256, 256>>>(et, dst, E);
    k_scan1<<<NB_SCAN, 256>>>();
    k_scan2<<<1, 256>>>();
    k_scan3<<<NB_SCAN, 256>>>();
    k_final<<<1, 1>>>(E);
    k_compact<<<(NSEG + 255) / 256, 256>>>();
    k_scatter<<<(E + 255) / 256, 256>>>(et, dst, src, E);

    const float* xin = x0;
    dim3 grid((N_NODES + 127) / 128, N_REL);

    for (int l = 0; l < 3; l++) {
        const float* bases = (const float*)d_in[3 + 4 * l];
        const float* comp  = (const float*)d_in[4 + 4 * l];
        const float* root  = (const float*)d_in[5 + 4 * l];
        const float* bias  = (const float*)d_in[6 + 4 * l];
        int dout = (l == 2) ? 8 : 64;

        k_W<<<(N_REL * 64 * dout + 255) / 256, 256>>>(bases, comp, dout);
        k_init<<<(N_NODES * dout + 255) / 256, 256>>>(xin, root, bias, dout);
        if (dout == 64) k_agg<64><<<grid, 256, SMEM64>>>(xin);
        else            k_agg<8><<<grid, 256, SMEM8>>>(xin);

        if (l == 0)      { k_relu<<<(N_NODES * 64 + 255) / 256, 256>>>(hA); xin = hA; }
        else if (l == 1) { k_relu<<<(N_NODES * 64 + 255) / 256, 256>>>(hB); xin = hB; }
        else             { k_lsm<<<(N_NODES + 255) / 256, 256>>>((float*)d_out); }
    }
}

// round 4
// speedup vs baseline: 1.5362x; 1.0930x over previous
#include <cuda_runtime.h>
#include <math.h>
#include <stdint.h>

// ---------------- problem constants ----------------
#define N_NODES 50000
#define N_REL   50
#define N_BASES 30
#define NSEG    (N_NODES * N_REL)
#define MAXE    1100000
#define SCAN_CHUNK 2048
#define NB2 ((NSEG + SCAN_CHUNK - 1) / SCAN_CHUNK)

// ---------------- static device scratch ----------------
__device__ int d_cnt[NSEG];
__device__ int d_off[NSEG + 1];
__device__ int d_cpt[NSEG + 1];
__device__ int d_cur[NSEG];
__device__ int d_coff[MAXE + 2];
__device__ int d_cdst[MAXE];
__device__ int d_srcn[MAXE];
__device__ unsigned long long d_agg[NB2];
__device__ unsigned long long d_incl[NB2];
__device__ int d_stat[NB2];
__device__ int d_bidc;
__device__ float d_W[N_REL * 64 * 64];
__device__ float d_msg[N_NODES * 64];
__device__ float d_hA[N_NODES * 64];
__device__ float d_hB[N_NODES * 64];

__device__ __forceinline__ float tf32r(float v) {
    uint32_t u;
    asm("cvt.rna.tf32.f32 %0, %1;" : "=r"(u) : "f"(v));
    return __uint_as_float(u);
}
__device__ __forceinline__ void red2(float* p, float a, float b) {
    asm volatile("red.global.add.v2.f32 [%0], {%1, %2};" :: "l"(p), "f"(a), "f"(b) : "memory");
}
__device__ __forceinline__ void red4(float* p, float a, float b, float c, float d) {
    asm volatile("red.global.add.v4.f32 [%0], {%1, %2, %3, %4};"
                 :: "l"(p), "f"(a), "f"(b), "f"(c), "f"(d) : "memory");
}

// ---------------- setup kernels ----------------
// zero cnt + msg + lookback state (runs every replay)
__global__ void k_zero() {
    int i = blockIdx.x * blockDim.x + threadIdx.x;
    if (i < NSEG) d_cnt[i] = 0;
    if (i < N_NODES * 64) d_msg[i] = 0.f;
    if (i < NB2) d_stat[i] = 0;
    if (i == 0) d_bidc = 0;
}

__global__ void k_hist(const int* __restrict__ et, const int* __restrict__ dst, int E) {
    int e = blockIdx.x * blockDim.x + threadIdx.x;
    if (e < E) atomicAdd(&d_cnt[et[e] * N_NODES + dst[e]], 1);
}

// single-pass decoupled-lookback scan of (cnt, cnt>0); writes off/cpt/cur + totals
__global__ void __launch_bounds__(256) k_scan() {
    __shared__ int sbid;
    __shared__ unsigned long long sexcl;
    __shared__ int ssum[256], sflg[256];
    int t = threadIdx.x;
    if (t == 0) sbid = atomicAdd(&d_bidc, 1);
    __syncthreads();
    int bid = sbid;
    int base = bid * SCAN_CHUNK + t * 8;
    int v[8], f[8];
    int run1 = 0, run2 = 0;
#pragma unroll
    for (int j = 0; j < 8; j++) {
        int idx = base + j;
        int c = (idx < NSEG) ? d_cnt[idx] : 0;
        v[j] = run1; f[j] = run2;
        run1 += c; run2 += (c > 0);
    }
    ssum[t] = run1; sflg[t] = run2;
    __syncthreads();
    for (int d = 1; d < 256; d <<= 1) {
        int a = 0, b = 0;
        if (t >= d) { a = ssum[t - d]; b = sflg[t - d]; }
        __syncthreads();
        if (t >= d) { ssum[t] += a; sflg[t] += b; }
        __syncthreads();
    }
    unsigned long long blockAgg =
        ((unsigned long long)(unsigned)ssum[255] << 32) | (unsigned)sflg[255];
    if (t == 0) {
        *((volatile unsigned long long*)&d_agg[bid]) = blockAgg;
        __threadfence();
        *((volatile int*)&d_stat[bid]) = 1;
    }
    if (t < 32) {   // warp 0: lookback
        unsigned long long excl = 0;
        int p = bid - 1;
        while (p >= 0) {
            int pi = p - t;
            int st;
            do {
                st = (pi >= 0) ? *((volatile int*)&d_stat[pi]) : 2;
            } while (__any_sync(0xffffffffu, st == 0));
            unsigned m2 = __ballot_sync(0xffffffffu, pi >= 0 && st == 2);
            if (m2) {
                int lead = __ffs(m2) - 1;
                unsigned long long vv = 0ull;
                if (pi >= 0) {
                    if (t < lead)       vv = *((volatile unsigned long long*)&d_agg[pi]);
                    else if (t == lead) vv = *((volatile unsigned long long*)&d_incl[pi]);
                }
                for (int o = 16; o > 0; o >>= 1) vv += __shfl_down_sync(0xffffffffu, vv, o);
                excl += __shfl_sync(0xffffffffu, vv, 0);
                break;
            } else {
                unsigned long long vv =
                    (pi >= 0) ? *((volatile unsigned long long*)&d_agg[pi]) : 0ull;
                for (int o = 16; o > 0; o >>= 1) vv += __shfl_down_sync(0xffffffffu, vv, o);
                excl += __shfl_sync(0xffffffffu, vv, 0);
                p -= 32;
            }
        }
        if (t == 0) {
            sexcl = excl;
            *((volatile unsigned long long*)&d_incl[bid]) = excl + blockAgg;
            __threadfence();
            *((volatile int*)&d_stat[bid]) = 2;
        }
    }
    __syncthreads();
    int exS = (int)(sexcl >> 32), exF = (int)(sexcl & 0xffffffffu);
    int ts = exS + ssum[t] - run1;
    int tf = exF + sflg[t] - run2;
#pragma unroll
    for (int j = 0; j < 8; j++) {
        int idx = base + j;
        if (idx < NSEG) {
            int o = ts + v[j];
            d_off[idx] = o; d_cur[idx] = o; d_cpt[idx] = tf + f[j];
        }
    }
    if (bid == NB2 - 1 && t == 255) {
        d_off[NSEG] = exS + ssum[255];
        d_cpt[NSEG] = exF + sflg[255];
    }
}

// fused compact CSR + counting-sort scatter
__global__ void k_cscat(const int* __restrict__ et, const int* __restrict__ dst,
                        const int* __restrict__ src, int E) {
    int i = blockIdx.x * blockDim.x + threadIdx.x;
    if (i < NSEG && d_cnt[i] > 0) {
        int c = d_cpt[i];
        d_coff[c] = d_off[i];
        d_cdst[c] = i % N_NODES;
    }
    if (i < E) {
        int key = et[i] * N_NODES + dst[i];
        int p = atomicAdd(&d_cur[key], 1);
        d_srcn[p] = src[i];
    }
    if (i == 0) d_coff[d_cpt[NSEG]] = E;
}

// ---------------- per-layer kernels ----------------
__global__ void k_W(const float* __restrict__ bases, const float* __restrict__ comp, int dout) {
    int idx = blockIdx.x * blockDim.x + threadIdx.x;
    int tot = N_REL * 64 * dout;
    if (idx >= tot) return;
    int r = idx / (64 * dout);
    int ko = idx - r * 64 * dout;
    float acc = 0.f;
#pragma unroll 6
    for (int b = 0; b < N_BASES; b++)
        acc += comp[r * N_BASES + b] * bases[b * 64 * dout + ko];
    d_W[idx] = tf32r(acc);
}

// Fused: per-relation mean aggregation + transform + vector RED accumulation.
// Block = 128 compact segments of one relation; warp owns 16 rows.
template <int DOUT>
__global__ void __launch_bounds__(256) k_agg(const float* __restrict__ x) {
    constexpr int WS = (DOUT == 64) ? 68 : 8;
    extern __shared__ float smem[];
    float* Ws = smem;                   // [64][WS]
    float* As = smem + 64 * WS;         // [128][68]
    int* sdst = (int*)(As + 128 * 68);  // [128]
    int* soB  = sdst + 128;             // [8][17]

    int r = blockIdx.y;
    int t = threadIdx.x, lane = t & 31, w = t >> 5;
    int* so = soB + w * 17;

    int baseC = d_cpt[r * N_NODES];
    int Cend  = d_cpt[(r + 1) * N_NODES];
    int row0  = blockIdx.x * 128;
    if (baseC + row0 >= Cend) return;

    const float* Wr = d_W + r * 64 * DOUT;
    if (DOUT == 64) {
        for (int i = t; i < 64 * 64; i += 256)
            Ws[(i >> 6) * 68 + (i & 63)] = Wr[i];
    } else {
        for (int i = t; i < 64 * 8; i += 256) Ws[i] = Wr[i];
    }

    int cbase = baseC + row0 + w * 16;
    if (lane <= 16) so[lane] = d_coff[min(cbase + lane, Cend)];
    if (lane < 16) {
        int ci = cbase + lane;
        sdst[w * 16 + lane] = (ci < Cend) ? d_cdst[ci] : -1;
    }
    __syncwarp();

    // --- MLP-friendly edge streaming ---
    float* myA = As + (w * 16) * 68;
    int eBase = so[0], eEnd = so[16];
    int ptrRow = 0, rowStart = eBase;
    float a0 = 0.f, a1 = 0.f;
    for (int cbeg = eBase; cbeg < eEnd; cbeg += 32) {
        int myE = cbeg + lane;
        int sn = 0;
        if (myE < eEnd) sn = __ldg(&d_srcn[myE]);   // coalesced prefetch
        int rid = 0;
#pragma unroll
        for (int q = 1; q < 16; q++) rid += (myE >= so[q]);
        int pk = sn | (rid << 20);                  // sn < 2^17
        int nIn = min(32, eEnd - cbeg);
        for (int j = 0; j < nIn; j++) {
            int pj = __shfl_sync(0xffffffffu, pk, j);
            int rj = pj >> 20;
            if (rj != ptrRow) {
                float inv = 1.f / (float)(cbeg + j - rowStart);
                myA[ptrRow * 68 + 2 * lane]     = tf32r(a0 * inv);
                myA[ptrRow * 68 + 2 * lane + 1] = tf32r(a1 * inv);
                a0 = 0.f; a1 = 0.f;
                ptrRow = rj;
                rowStart = cbeg + j;
            }
            int snj = pj & 0xFFFFF;
            float2 xv = *(const float2*)(x + snj * 64 + 2 * lane);
            a0 += xv.x; a1 += xv.y;
        }
    }
    if (eEnd > eBase) {
        float inv = 1.f / (float)(eEnd - rowStart);
        myA[ptrRow * 68 + 2 * lane]     = tf32r(a0 * inv);
        myA[ptrRow * 68 + 2 * lane + 1] = tf32r(a1 * inv);
    }
    __syncthreads();

    if (DOUT == 64) {
        int g = lane >> 2, q = lane & 3;
        const float* Ar0 = As + (w * 16 + g) * 68;
        const float* Ar8 = Ar0 + 8 * 68;
        float acc[8][4];
#pragma unroll
        for (int j = 0; j < 8; j++)
#pragma unroll
            for (int i = 0; i < 4; i++) acc[j][i] = 0.f;
#pragma unroll
        for (int kk = 0; kk < 8; kk++) {
            int k0 = kk * 8;
            uint32_t A0 = __float_as_uint(Ar0[k0 + q]);
            uint32_t A1 = __float_as_uint(Ar8[k0 + q]);
            uint32_t A2 = __float_as_uint(Ar0[k0 + q + 4]);
            uint32_t A3 = __float_as_uint(Ar8[k0 + q + 4]);
#pragma unroll
            for (int j = 0; j < 8; j++) {
                uint32_t B0 = __float_as_uint(Ws[(k0 + q) * 68 + j * 8 + g]);
                uint32_t B1 = __float_as_uint(Ws[(k0 + q + 4) * 68 + j * 8 + g]);
                asm volatile(
                    "mma.sync.aligned.m16n8k8.row.col.f32.tf32.tf32.f32 "
                    "{%0,%1,%2,%3}, {%4,%5,%6,%7}, {%8,%9}, {%0,%1,%2,%3};"
                    : "+f"(acc[j][0]), "+f"(acc[j][1]), "+f"(acc[j][2]), "+f"(acc[j][3])
                    : "r"(A0), "r"(A1), "r"(A2), "r"(A3), "r"(B0), "r"(B1));
            }
        }
        int dA = sdst[w * 16 + g];
        int dB = sdst[w * 16 + g + 8];
#pragma unroll
        for (int j = 0; j < 8; j++) {
            int col = j * 8 + 2 * q;
            if (dA >= 0) red2(&d_msg[dA * 64 + col], acc[j][0], acc[j][1]);
            if (dB >= 0) red2(&d_msg[dB * 64 + col], acc[j][2], acc[j][3]);
        }
    } else {
        int row = lane >> 1;
        int c0 = (lane & 1) * 4;
        const float* Ar = As + (w * 16 + row) * 68;
        float s0 = 0.f, s1 = 0.f, s2 = 0.f, s3 = 0.f;
#pragma unroll
        for (int k = 0; k < 64; k++) {
            float a = Ar[k];
            float4 b = *(const float4*)&Ws[k * 8 + c0];
            s0 += a * b.x; s1 += a * b.y; s2 += a * b.z; s3 += a * b.w;
        }
        int dn = sdst[w * 16 + row];
        if (dn >= 0) red4(&d_msg[dn * 8 + c0], s0, s1, s2, s3);
    }
}

// epilogue: h = relu(msg + x@root + bias); also re-zero msg for next layer
__global__ void k_rootrelu(const float* __restrict__ x, const float* __restrict__ root,
                           const float* __restrict__ bias, float* __restrict__ h) {
    int idx = blockIdx.x * blockDim.x + threadIdx.x;
    if (idx >= N_NODES * 64) return;
    int n = idx >> 6, o = idx & 63;
    float acc = bias[o] + d_msg[idx];
    d_msg[idx] = 0.f;
    const float* xr = x + n * 64;
#pragma unroll 16
    for (int i = 0; i < 64; i++) acc += xr[i] * root[i * 64 + o];
    h[idx] = acc > 0.f ? acc : 0.f;
}

// final epilogue: out = log_softmax(msg + x@root + bias)
__global__ void k_rootlsm(const float* __restrict__ x, const float* __restrict__ root,
                          const float* __restrict__ bias, float* __restrict__ out) {
    int n = blockIdx.x * blockDim.x + threadIdx.x;
    if (n >= N_NODES) return;
    float v[8];
#pragma unroll
    for (int c = 0; c < 8; c++) v[c] = bias[c] + d_msg[n * 8 + c];
    const float* xr = x + n * 64;
    for (int i = 0; i < 64; i++) {
        float xv = xr[i];
#pragma unroll
        for (int c = 0; c < 8; c++) v[c] += xv * root[i * 8 + c];
    }
    float m = -1e30f;
#pragma unroll
    for (int c = 0; c < 8; c++) m = fmaxf(m, v[c]);
    float s = 0.f;
#pragma unroll
    for (int c = 0; c < 8; c++) s += expf(v[c] - m);
    float ls = logf(s) + m;
#pragma unroll
    for (int c = 0; c < 8; c++) out[n * 8 + c] = v[c] - ls;
}

// ---------------- launch ----------------
extern "C" void kernel_launch(void* const* d_in, const int* in_sizes, int n_in,
                              void* d_out, int out_size) {
    const float* x0 = (const float*)d_in[0];
    const int* ei = (const int*)d_in[1];
    const int* et = (const int*)d_in[2];
    int E = in_sizes[2];
    const int* src = ei;
    const int* dst = ei + E;

    void *pA, *pB;
    cudaGetSymbolAddress(&pA, d_hA);
    cudaGetSymbolAddress(&pB, d_hB);
    float* hA = (float*)pA;
    float* hB = (float*)pB;

    const int SMEM64 = (64 * 68 + 128 * 68) * 4 + 128 * 4 + 8 * 17 * 4;
    const int SMEM8  = (64 * 8  + 128 * 68) * 4 + 128 * 4 + 8 * 17 * 4;
    cudaFuncSetAttribute(k_agg<64>, cudaFuncAttributeMaxDynamicSharedMemorySize, SMEM64);
    cudaFuncSetAttribute(k_agg<8>,  cudaFuncAttributeMaxDynamicSharedMemorySize, SMEM8);

    const int NZ = N_NODES * 64;   // >= NSEG
    k_zero<<<(NZ + 255) / 256, 256>>>();                       // 1
    k_hist<<<(E + 255) / 256, 256>>>(et, dst, E);              // 2
    k_scan<<<NB2, 256>>>();                                    // 3
    k_cscat<<<(NSEG + 255) / 256, 256>>>(et, dst, src, E);     // 4

    dim3 grid((N_NODES + 127) / 128, N_REL);

    // layer 0
    k_W<<<(N_REL * 64 * 64 + 255) / 256, 256>>>((const float*)d_in[3], (const float*)d_in[4], 64); // 5
    k_agg<64><<<grid, 256, SMEM64>>>(x0);                      // 6  <- ncu target
    k_rootrelu<<<(NZ + 255) / 256, 256>>>(x0, (const float*)d_in[5], (const float*)d_in[6], hA);
    // layer 1
    k_W<<<(N_REL * 64 * 64 + 255) / 256, 256>>>((const float*)d_in[7], (const float*)d_in[8], 64);
    k_agg<64><<<grid, 256, SMEM64>>>(hA);
    k_rootrelu<<<(NZ + 255) / 256, 256>>>(hA, (const float*)d_in[9], (const float*)d_in[10], hB);
    // layer 2
    k_W<<<(N_REL * 64 * 8 + 255) / 256, 256>>>((const float*)d_in[11], (const float*)d_in[12], 8);
    k_agg<8><<<grid, 256, SMEM8>>>(hB);
    k_rootlsm<<<(N_NODES + 255) / 256, 256>>>(hB, (const float*)d_in[13], (const float*)d_in[14],
                                              (float*)d_out);
}